// round 15
// baseline (speedup 1.0000x reference)
#include <cuda_runtime.h>
#include <cstdint>

typedef unsigned long long ull;

// ---------------- problem constants ----------------
#define MF    1024
#define NCC   512
#define KSN   24
#define NAN_  60
#define CON   128
#define NBB   2
#define R2C   0.16f
#define SCV   18.033688011112043f   // log2(e)/SIGMA
#define EPSV  1e-5f

#define FEAT_OFF  (NBB*3*NCC)                 // 3072
#define FEAT_N    (NBB*CON*NCC*NAN_)          // 7864320
#define ANCH_OFF  (FEAT_OFF + FEAT_N)
#define GRP       (NCC*NAN_)                  // 30720
#define NCTA      (NBB*NCC*2)                 // 2048

// ---------------- packed f32x2 helpers ----------------
#define PAK(d,a,b)    asm("mov.b64 %0, {%1,%2};" : "=l"(d) : "f"(a), "f"(b))
#define UPK(a,b,d)    asm("mov.b64 {%0,%1}, %2;" : "=f"(a), "=f"(b) : "l"(d))
#define UPKU(a,b,d)   asm("mov.b64 {%0,%1}, %2;" : "=r"(a), "=r"(b) : "l"(d))
#define PAKU(d,a,b)   asm("mov.b64 %0, {%1,%2};" : "=l"(d) : "r"(a), "r"(b))
#define FMA2(d,a,b,c) asm("fma.rn.f32x2 %0, %1, %2, %3;" : "=l"(d) : "l"(a), "l"(b), "l"(c))
#define ADD2(d,a,b)   asm("add.rn.f32x2 %0, %1, %2;" : "=l"(d) : "l"(a), "l"(b))

__device__ __forceinline__ float ex2f(float x) {
    float r; asm("ex2.approx.ftz.f32 %0, %1;" : "=f"(r) : "f"(x)); return r;
}

// global stats state (zero-init; re-zeroed by last CTA each launch)
__device__ float    g_sum[NBB*CON];
__device__ float    g_sqs[NBB*CON];
__device__ float    g_mu[NBB*CON];
__device__ float    g_inv[NBB*CON];
__device__ unsigned g_tick;

// magic-constant exp2 (R7-validated): z = t + 1.5*2^23 ; r = t - (z-c) in [-0.5,0.5]
// 2^r deg-4 Taylor; exponent applied via (z_bits << 23) bit-add on the ALU pipe.
#define MAGICC 12582912.0f      // 1.5 * 2^23
#define EC1 0.6931471806f       // ln2
#define EC2 0.2402265070f       // ln2^2/2
#define EC3 0.0555041087f       // ln2^3/6
#define EC4 0.0096181291f       // ln2^4/24

struct PolyC { ull cc, negone, one, c1, c2, c3, c4; };

// one pair (2 frags) x 6 kernel points; first NPOLY j's use the packed magic exp2
template<int NPOLY>
__device__ __forceinline__ void pair_body(const float4* __restrict__ lbv, int q,
                                          const ull* kx2, const ull* ky2, const ull* kz2,
                                          ull* acc2, const PolyC& pc)
{
    float4 A = lbv[2*q];       // dx0,dx1,dy0,dy1
    float4 B = lbv[2*q+1];     // dz0,dz1,p0,p1
    ull dx2, dy2, dz2, pp2;
    PAK(dx2, A.x, A.y); PAK(dy2, A.z, A.w);
    PAK(dz2, B.x, B.y); PAK(pp2, B.z, B.w);
    #pragma unroll
    for (int j = 0; j < 6; j++) {
        ull t2;
        FMA2(t2, kz2[j], dz2, pp2);
        FMA2(t2, ky2[j], dy2, t2);
        FMA2(t2, kx2[j], dx2, t2);
        if (j < NPOLY) {
            ull z2, zi2, r2, v2;
            ADD2(z2, t2, pc.cc);                    // round t to int (in mantissa)
            FMA2(zi2, pc.negone, pc.cc, z2);        // zi = z - c  (= round(t))
            FMA2(r2,  pc.negone, zi2,  t2);         // r = t - round(t), |r|<=0.5
            FMA2(v2, pc.c4, r2, pc.c3);
            FMA2(v2, v2, r2, pc.c2);
            FMA2(v2, v2, r2, pc.c1);
            FMA2(v2, v2, r2, pc.one);               // 2^r
            unsigned zl, zh, vl, vh;
            UPKU(zl, zh, z2);
            UPKU(vl, vh, v2);
            unsigned rl = vl + (zl << 23);          // apply 2^round(t) via exponent bits
            unsigned rh = vh + (zh << 23);
            ull w2; PAKU(w2, rl, rh);
            ADD2(acc2[j], acc2[j], w2);
        } else {
            float tl, th; UPK(tl, th, t2);
            float wl = ex2f(tl);
            float wh = ex2f(th);
            ull w2; PAK(w2, wl, wh);
            ADD2(acc2[j], acc2[j], w2);
        }
    }
}

// One CTA = (cloud point, anchor-half). 128 threads.
__global__ void __launch_bounds__(128) prop_kernel(
    const float* __restrict__ frag,    // [1024,3]
    const float* __restrict__ clouds,  // [2,3,512]
    const float* __restrict__ kern,    // [24,60,3]
    const float* __restrict__ W,       // [128,24]
    float* __restrict__ out)
{
    __shared__ __align__(16) float4 listbuf[MF];      // phase A/B list; phase C feat stage
    __shared__ __align__(16) float  wts_s[KSN][30];
    __shared__ int warp_tot[4];
    __shared__ unsigned s_tick;

    const int tid   = threadIdx.x;
    const int lane  = tid & 31;
    const int widx  = tid >> 5;
    const int blk   = blockIdx.x;
    const int point = blk >> 1;
    const int half  = blk & 1;
    const int b     = point >> 9;
    const int n     = point & (NCC-1);

    const float cx = clouds[b*3*NCC +         n];
    const float cy = clouds[b*3*NCC +   NCC + n];
    const float cz = clouds[b*3*NCC + 2*NCC + n];

    // ---------- Phase A: masked-frag compaction (pair-interleaved layout) ----------
    float fr[24];
    {
        const float4* fp = reinterpret_cast<const float4*>(frag) + tid*6;
        #pragma unroll
        for (int u = 0; u < 6; u++) {
            float4 q = fp[u];
            fr[u*4+0] = q.x; fr[u*4+1] = q.y; fr[u*4+2] = q.z; fr[u*4+3] = q.w;
        }
    }
    float lx[8], ly[8], lz[8], lp[8];
    unsigned pm = 0;
    #pragma unroll
    for (int j = 0; j < 8; j++) {
        float dx = fr[j*3+0] - cx;
        float dy = fr[j*3+1] - cy;
        float dz = fr[j*3+2] - cz;
        float d2 = dx*dx + dy*dy + dz*dz;
        lx[j] = dx; ly[j] = dy; lz[j] = dz; lp[j] = -d2 * SCV;
        if (d2 < R2C) pm |= (1u << j);
    }
    int c0 = __popc(pm);
    int x = c0;
    #pragma unroll
    for (int off = 1; off < 32; off <<= 1) {
        int y = __shfl_up_sync(0xffffffffu, x, off);
        if (lane >= off) x += y;
    }
    if (lane == 31) warp_tot[widx] = x;
    __syncthreads();
    int wpre = 0, cnt = 0;
    #pragma unroll
    for (int w = 0; w < 4; w++) {
        int t = warp_tot[w];
        if (w < widx) wpre += t;
        cnt += t;
    }
    int ofs = wpre + x - c0;
    float* lb = reinterpret_cast<float*>(listbuf);
    #pragma unroll
    for (int j = 0; j < 8; j++) {
        if (pm & (1u << j)) {
            int base = (ofs >> 1)*8 + (ofs & 1);
            lb[base+0] = lx[j]; lb[base+2] = ly[j];
            lb[base+4] = lz[j]; lb[base+6] = lp[j];
            ofs++;
        }
    }
    __syncthreads();

    // ---------- Phase B: RBF accumulation (f32x2 dots, f=1/12 magic exp2) ----------
    const float invc = 1.0f / (float)(cnt + 1);
    const int a_local = tid >> 2;
    const int kq      = tid & 3;
    if (a_local < 30) {
        const int a = half*30 + a_local;
        PolyC pc;
        PAK(pc.cc, MAGICC, MAGICC);
        PAK(pc.negone, -1.0f, -1.0f);
        PAK(pc.one, 1.0f, 1.0f);
        PAK(pc.c1, EC1, EC1); PAK(pc.c2, EC2, EC2);
        PAK(pc.c3, EC3, EC3); PAK(pc.c4, EC4, EC4);

        ull kx2[6], ky2[6], kz2[6], acc2[6];
        float cf[6];
        #pragma unroll
        for (int j = 0; j < 6; j++) {
            int k = kq*6 + j;
            const float* kp = kern + ((size_t)k*NAN_ + a)*3;
            float rx = kp[0], ry = kp[1], rz = kp[2];
            float k2 = rx*rx + ry*ry + rz*rz;
            cf[j] = ex2f(-k2 * SCV);
            float kx = rx * (2.0f*SCV), ky = ry * (2.0f*SCV), kz = rz * (2.0f*SCV);
            PAK(kx2[j], kx, kx); PAK(ky2[j], ky, ky); PAK(kz2[j], kz, kz);
            acc2[j] = 0ull;
        }
        const float4* lbv = listbuf;
        const int np = cnt >> 1;
        int q = 0;
        #pragma unroll 1
        for (; q + 2 <= np; q += 2) {
            pair_body<0>(lbv, q,   kx2, ky2, kz2, acc2, pc);   // all-MUFU pair
            pair_body<1>(lbv, q+1, kx2, ky2, kz2, acc2, pc);   // 1-of-12 magic poly
        }
        if (q < np) pair_body<0>(lbv, q, kx2, ky2, kz2, acc2, pc);

        float tail[6];
        #pragma unroll
        for (int j = 0; j < 6; j++) tail[j] = 0.f;
        if (cnt & 1) {
            int base = np*8;
            float dx = lb[base], dy = lb[base+2], dz = lb[base+4], p = lb[base+6];
            #pragma unroll
            for (int j = 0; j < 6; j++) {
                float kx, ky, kz, jk;
                UPK(kx, jk, kx2[j]); UPK(ky, jk, ky2[j]); UPK(kz, jk, kz2[j]);
                float t = fmaf(kx, dx, fmaf(ky, dy, fmaf(kz, dz, p)));
                tail[j] = ex2f(t);
            }
        }
        #pragma unroll
        for (int j = 0; j < 6; j++) {
            float lo, hi; UPK(lo, hi, acc2[j]);
            wts_s[kq*6 + j][a_local] = (lo + hi + tail[j]) * cf[j] * invc;
        }
    }
    __syncthreads();

    // ---------- Phase C: feats = W @ wts, atomic partial stats ----------
    ull wk2[24];
    {
        const float* wp = W + tid*KSN;
        #pragma unroll
        for (int k = 0; k < 24; k++) { float w = wp[k]; PAK(wk2[k], w, w); }
    }
    float* fsm = reinterpret_cast<float*>(listbuf);   // 128*30 floats
    float ls = 0.f, lss = 0.f;
    #pragma unroll 1
    for (int al2 = 0; al2 < 15; al2++) {
        ull s2 = 0ull;
        #pragma unroll
        for (int k = 0; k < 24; k++) {
            ull wt2 = *reinterpret_cast<const ull*>(&wts_s[k][2*al2]);  // LDS.64 broadcast
            FMA2(s2, wk2[k], wt2, s2);
        }
        *reinterpret_cast<ull*>(&fsm[tid*30 + 2*al2]) = s2;
        float slo, shi; UPK(slo, shi, s2);
        ls += slo + shi;
        lss = fmaf(slo, slo, lss); lss = fmaf(shi, shi, lss);
    }
    atomicAdd(&g_sum[b*CON + tid], ls);
    atomicAdd(&g_sqs[b*CON + tid], lss);
    __syncthreads();

    // staged store: 128 channels x 30 anchors
    float* fout = out + FEAT_OFF;
    #pragma unroll 1
    for (int e = tid; e < CON*30; e += 128) {
        int c  = e / 30;
        int al = e - c*30;
        int oidx = (((b*CON + c)*NCC) + n)*NAN_ + half*30 + al;
        fout[oidx] = fsm[e];
    }

    // ---------- ticket epilogue: last CTA computes mu/inv and resets state ----------
    __threadfence();                      // make this CTA's atomics visible before ticket
    __syncthreads();
    if (tid == 0) s_tick = atomicAdd(&g_tick, 1u);
    __syncthreads();
    if (s_tick == NCTA - 1) {
        #pragma unroll
        for (int bc = tid; bc < NBB*CON; bc += 128) {
            float mu  = g_sum[bc] * (1.0f/GRP);
            float var = fmaf(-mu, mu, g_sqs[bc] * (1.0f/GRP));
            g_mu[bc]  = mu;
            g_inv[bc] = rsqrtf(var + EPSV);
            g_sum[bc] = 0.f;              // reset for next graph replay
            g_sqs[bc] = 0.f;
        }
        __threadfence();
        __syncthreads();
        if (tid == 0) g_tick = 0u;
    }
}

// Wide-grid single-pass normalize + ReLU. 30 chunks per (b,c), 256 float4 each,
// one element per thread (max grid-level latency hiding).
__global__ void __launch_bounds__(256) norm_kernel(
    const float* __restrict__ clouds,
    const float* __restrict__ anchors,
    float* __restrict__ out)
{
    const int bc    = blockIdx.x / 30;
    const int chunk = blockIdx.x - bc*30;
    const float mu  = g_mu[bc];
    const float inv = g_inv[bc];
    float4* p4 = reinterpret_cast<float4*>(out + FEAT_OFF + (size_t)bc*GRP) + chunk*256;
    float4 v = p4[threadIdx.x];
    v.x = fmaxf((v.x - mu)*inv, 0.f);
    v.y = fmaxf((v.y - mu)*inv, 0.f);
    v.z = fmaxf((v.z - mu)*inv, 0.f);
    v.w = fmaxf((v.w - mu)*inv, 0.f);
    p4[threadIdx.x] = v;

    if (blockIdx.x == 0) {
        for (int i = threadIdx.x; i < FEAT_OFF; i += 256) out[i] = clouds[i];
    }
    if (blockIdx.x == 30) {
        for (int i = threadIdx.x; i < 540; i += 256) out[ANCH_OFF + i] = anchors[i];
    }
}

extern "C" void kernel_launch(void* const* d_in, const int* in_sizes, int n_in,
                              void* d_out, int out_size) {
    const float* frag    = (const float*)d_in[0];
    const float* clouds  = (const float*)d_in[1];
    const float* kern    = (const float*)d_in[2];
    const float* W       = (const float*)d_in[3];
    const float* anchors = (const float*)d_in[4];
    float* out = (float*)d_out;

    prop_kernel<<<NCTA, 128>>>(frag, clouds, kern, W, out);
    norm_kernel<<<NBB*CON*30, 256>>>(clouds, anchors, out);
}

// round 16
// speedup vs baseline: 1.0302x; 1.0302x over previous
#include <cuda_runtime.h>
#include <cstdint>

typedef unsigned long long ull;

// ---------------- problem constants ----------------
#define MF    1024
#define NCC   512
#define KSN   24
#define NAN_  60
#define CON   128
#define NBB   2
#define R2C   0.16f
#define SCV   18.033688011112043f   // log2(e)/SIGMA
#define EPSV  1e-5f

#define FEAT_OFF  (NBB*3*NCC)                 // 3072
#define FEAT_N    (NBB*CON*NCC*NAN_)          // 7864320
#define ANCH_OFF  (FEAT_OFF + FEAT_N)
#define GRP       (NCC*NAN_)                  // 30720
#define NCTA      (NBB*NCC*2)                 // 2048

// ---------------- packed f32x2 helpers ----------------
#define PAK(d,a,b)    asm("mov.b64 %0, {%1,%2};" : "=l"(d) : "f"(a), "f"(b))
#define UPK(a,b,d)    asm("mov.b64 {%0,%1}, %2;" : "=f"(a), "=f"(b) : "l"(d))
#define FMA2(d,a,b,c) asm("fma.rn.f32x2 %0, %1, %2, %3;" : "=l"(d) : "l"(a), "l"(b), "l"(c))
#define MUL2(d,a,b)   asm("mul.rn.f32x2 %0, %1, %2;" : "=l"(d) : "l"(a), "l"(b))
#define ADD2(d,a,b)   asm("add.rn.f32x2 %0, %1, %2;" : "=l"(d) : "l"(a), "l"(b))

__device__ __forceinline__ float ex2f(float x) {
    float r; asm("ex2.approx.ftz.f32 %0, %1;" : "=f"(r) : "f"(x)); return r;
}

// global stats state (zero-init; re-zeroed by last CTA each launch)
__device__ float    g_sum[NBB*CON];
__device__ float    g_sqs[NBB*CON];
__device__ float    g_mu[NBB*CON];
__device__ float    g_inv[NBB*CON];
__device__ unsigned g_tick;

// deg-5 Taylor of 2^z at z0=-0.4416, z = t/16 in [-0.8832, 0]
#define PB0 0.736306f
#define PB1 0.510370f
#define PB2 0.176882f
#define PB3 0.0408687f
#define PB4 0.0070820f
#define PB5 0.00098177f
#define PINV16 0.0625f
#define PCEN   0.4416f

struct PolyC { ull inv16, cen, b0, b1, b2, b3, b4, b5; };

// one pair (2 frags) x 6 kernel points; first NPOLY j's use the fma-pipe poly
template<int NPOLY>
__device__ __forceinline__ void pair_body(const float4* __restrict__ lbv, int q,
                                          const ull* kx2, const ull* ky2, const ull* kz2,
                                          ull* acc2, const PolyC& pc)
{
    float4 A = lbv[2*q];       // dx0,dx1,dy0,dy1
    float4 B = lbv[2*q+1];     // dz0,dz1,p0,p1
    ull dx2, dy2, dz2, pp2;
    PAK(dx2, A.x, A.y); PAK(dy2, A.z, A.w);
    PAK(dz2, B.x, B.y); PAK(pp2, B.z, B.w);
    #pragma unroll
    for (int j = 0; j < 6; j++) {
        ull t2;
        FMA2(t2, kz2[j], dz2, pp2);
        FMA2(t2, ky2[j], dy2, t2);
        FMA2(t2, kx2[j], dx2, t2);
        if (j < NPOLY) {
            ull u2, v;
            FMA2(u2, t2, pc.inv16, pc.cen);        // u = t/16 + 0.4416
            FMA2(v, pc.b5, u2, pc.b4);
            FMA2(v, v, u2, pc.b3);
            FMA2(v, v, u2, pc.b2);
            FMA2(v, v, u2, pc.b1);
            FMA2(v, v, u2, pc.b0);
            MUL2(v, v, v); MUL2(v, v, v); MUL2(v, v, v); MUL2(v, v, v);  // ^16
            ADD2(acc2[j], acc2[j], v);
        } else {
            float tl, th; UPK(tl, th, t2);
            float wl = ex2f(tl);
            float wh = ex2f(th);
            ull w2; PAK(w2, wl, wh);
            ADD2(acc2[j], acc2[j], w2);
        }
    }
}

// One CTA = (cloud point, anchor-half). 128 threads.
__global__ void __launch_bounds__(128) prop_kernel(
    const float* __restrict__ frag,    // [1024,3]
    const float* __restrict__ clouds,  // [2,3,512]
    const float* __restrict__ kern,    // [24,60,3]
    const float* __restrict__ W,       // [128,24]
    float* __restrict__ out)
{
    __shared__ __align__(16) float4 listbuf[MF];      // phase A/B list; phase C feat stage
    __shared__ __align__(16) float  wts_s[KSN][30];
    __shared__ int warp_tot[4];
    __shared__ unsigned s_tick;

    const int tid   = threadIdx.x;
    const int lane  = tid & 31;
    const int widx  = tid >> 5;
    const int blk   = blockIdx.x;
    const int point = blk >> 1;
    const int half  = blk & 1;
    const int b     = point >> 9;
    const int n     = point & (NCC-1);

    const float cx = clouds[b*3*NCC +         n];
    const float cy = clouds[b*3*NCC +   NCC + n];
    const float cz = clouds[b*3*NCC + 2*NCC + n];

    // ---------- Phase A: masked-frag compaction (pair-interleaved layout) ----------
    float fr[24];
    {
        const float4* fp = reinterpret_cast<const float4*>(frag) + tid*6;
        #pragma unroll
        for (int u = 0; u < 6; u++) {
            float4 q = fp[u];
            fr[u*4+0] = q.x; fr[u*4+1] = q.y; fr[u*4+2] = q.z; fr[u*4+3] = q.w;
        }
    }
    float lx[8], ly[8], lz[8], lp[8];
    unsigned pm = 0;
    #pragma unroll
    for (int j = 0; j < 8; j++) {
        float dx = fr[j*3+0] - cx;
        float dy = fr[j*3+1] - cy;
        float dz = fr[j*3+2] - cz;
        float d2 = dx*dx + dy*dy + dz*dz;
        lx[j] = dx; ly[j] = dy; lz[j] = dz; lp[j] = -d2 * SCV;
        if (d2 < R2C) pm |= (1u << j);
    }
    int c0 = __popc(pm);
    int x = c0;
    #pragma unroll
    for (int off = 1; off < 32; off <<= 1) {
        int y = __shfl_up_sync(0xffffffffu, x, off);
        if (lane >= off) x += y;
    }
    if (lane == 31) warp_tot[widx] = x;
    __syncthreads();
    int wpre = 0, cnt = 0;
    #pragma unroll
    for (int w = 0; w < 4; w++) {
        int t = warp_tot[w];
        if (w < widx) wpre += t;
        cnt += t;
    }
    int ofs = wpre + x - c0;
    float* lb = reinterpret_cast<float*>(listbuf);
    #pragma unroll
    for (int j = 0; j < 8; j++) {
        if (pm & (1u << j)) {
            int base = (ofs >> 1)*8 + (ofs & 1);
            lb[base+0] = lx[j]; lb[base+2] = ly[j];
            lb[base+4] = lz[j]; lb[base+6] = lp[j];
            ofs++;
        }
    }
    __syncthreads();

    // ---------- Phase B: RBF accumulation (f32x2 dots, f=1/12 Taylor poly — best measured) ----------
    const float invc = 1.0f / (float)(cnt + 1);
    const int a_local = tid >> 2;
    const int kq      = tid & 3;
    if (a_local < 30) {
        const int a = half*30 + a_local;
        PolyC pc;
        PAK(pc.inv16, PINV16, PINV16); PAK(pc.cen, PCEN, PCEN);
        PAK(pc.b0, PB0, PB0); PAK(pc.b1, PB1, PB1); PAK(pc.b2, PB2, PB2);
        PAK(pc.b3, PB3, PB3); PAK(pc.b4, PB4, PB4); PAK(pc.b5, PB5, PB5);

        ull kx2[6], ky2[6], kz2[6], acc2[6];
        float cf[6];
        #pragma unroll
        for (int j = 0; j < 6; j++) {
            int k = kq*6 + j;
            const float* kp = kern + ((size_t)k*NAN_ + a)*3;
            float rx = kp[0], ry = kp[1], rz = kp[2];
            float k2 = rx*rx + ry*ry + rz*rz;
            cf[j] = ex2f(-k2 * SCV);
            float kx = rx * (2.0f*SCV), ky = ry * (2.0f*SCV), kz = rz * (2.0f*SCV);
            PAK(kx2[j], kx, kx); PAK(ky2[j], ky, ky); PAK(kz2[j], kz, kz);
            acc2[j] = 0ull;
        }
        const float4* lbv = listbuf;
        const int np = cnt >> 1;
        int q = 0;
        #pragma unroll 1
        for (; q + 2 <= np; q += 2) {
            pair_body<0>(lbv, q,   kx2, ky2, kz2, acc2, pc);   // all-MUFU pair
            pair_body<1>(lbv, q+1, kx2, ky2, kz2, acc2, pc);   // 1-of-12 poly
        }
        if (q < np) pair_body<0>(lbv, q, kx2, ky2, kz2, acc2, pc);

        float tail[6];
        #pragma unroll
        for (int j = 0; j < 6; j++) tail[j] = 0.f;
        if (cnt & 1) {
            int base = np*8;
            float dx = lb[base], dy = lb[base+2], dz = lb[base+4], p = lb[base+6];
            #pragma unroll
            for (int j = 0; j < 6; j++) {
                float kx, ky, kz, jk;
                UPK(kx, jk, kx2[j]); UPK(ky, jk, ky2[j]); UPK(kz, jk, kz2[j]);
                float t = fmaf(kx, dx, fmaf(ky, dy, fmaf(kz, dz, p)));
                tail[j] = ex2f(t);
            }
        }
        #pragma unroll
        for (int j = 0; j < 6; j++) {
            float lo, hi; UPK(lo, hi, acc2[j]);
            wts_s[kq*6 + j][a_local] = (lo + hi + tail[j]) * cf[j] * invc;
        }
    }
    __syncthreads();

    // ---------- Phase C: feats = W @ wts, atomic partial stats ----------
    ull wk2[24];
    {
        const float* wp = W + tid*KSN;
        #pragma unroll
        for (int k = 0; k < 24; k++) { float w = wp[k]; PAK(wk2[k], w, w); }
    }
    float* fsm = reinterpret_cast<float*>(listbuf);   // 128*30 floats
    float ls = 0.f, lss = 0.f;
    #pragma unroll 1
    for (int al2 = 0; al2 < 15; al2++) {
        ull s2 = 0ull;
        #pragma unroll
        for (int k = 0; k < 24; k++) {
            ull wt2 = *reinterpret_cast<const ull*>(&wts_s[k][2*al2]);  // LDS.64 broadcast
            FMA2(s2, wk2[k], wt2, s2);
        }
        *reinterpret_cast<ull*>(&fsm[tid*30 + 2*al2]) = s2;
        float slo, shi; UPK(slo, shi, s2);
        ls += slo + shi;
        lss = fmaf(slo, slo, lss); lss = fmaf(shi, shi, lss);
    }
    atomicAdd(&g_sum[b*CON + tid], ls);
    atomicAdd(&g_sqs[b*CON + tid], lss);
    __syncthreads();

    // staged store: 128 channels x 30 anchors
    float* fout = out + FEAT_OFF;
    #pragma unroll 1
    for (int e = tid; e < CON*30; e += 128) {
        int c  = e / 30;
        int al = e - c*30;
        int oidx = (((b*CON + c)*NCC) + n)*NAN_ + half*30 + al;
        fout[oidx] = fsm[e];
    }

    // ---------- ticket epilogue: last CTA computes mu/inv and resets state ----------
    __threadfence();                      // make this CTA's atomics visible before ticket
    __syncthreads();
    if (tid == 0) s_tick = atomicAdd(&g_tick, 1u);
    __syncthreads();
    if (s_tick == NCTA - 1) {
        #pragma unroll
        for (int bc = tid; bc < NBB*CON; bc += 128) {
            float mu  = g_sum[bc] * (1.0f/GRP);
            float var = fmaf(-mu, mu, g_sqs[bc] * (1.0f/GRP));
            g_mu[bc]  = mu;
            g_inv[bc] = rsqrtf(var + EPSV);
            g_sum[bc] = 0.f;              // reset for next graph replay
            g_sqs[bc] = 0.f;
        }
        __threadfence();
        __syncthreads();
        if (tid == 0) g_tick = 0u;
    }
}

// Wide-grid single-pass normalize + ReLU. 30 chunks per (b,c), 256 float4 each,
// one element per thread (max grid-level latency hiding).
__global__ void __launch_bounds__(256) norm_kernel(
    const float* __restrict__ clouds,
    const float* __restrict__ anchors,
    float* __restrict__ out)
{
    const int bc    = blockIdx.x / 30;
    const int chunk = blockIdx.x - bc*30;
    const float mu  = g_mu[bc];
    const float inv = g_inv[bc];
    float4* p4 = reinterpret_cast<float4*>(out + FEAT_OFF + (size_t)bc*GRP) + chunk*256;
    float4 v = p4[threadIdx.x];
    v.x = fmaxf((v.x - mu)*inv, 0.f);
    v.y = fmaxf((v.y - mu)*inv, 0.f);
    v.z = fmaxf((v.z - mu)*inv, 0.f);
    v.w = fmaxf((v.w - mu)*inv, 0.f);
    p4[threadIdx.x] = v;

    if (blockIdx.x == 0) {
        for (int i = threadIdx.x; i < FEAT_OFF; i += 256) out[i] = clouds[i];
    }
    if (blockIdx.x == 30) {
        for (int i = threadIdx.x; i < 540; i += 256) out[ANCH_OFF + i] = anchors[i];
    }
}

extern "C" void kernel_launch(void* const* d_in, const int* in_sizes, int n_in,
                              void* d_out, int out_size) {
    const float* frag    = (const float*)d_in[0];
    const float* clouds  = (const float*)d_in[1];
    const float* kern    = (const float*)d_in[2];
    const float* W       = (const float*)d_in[3];
    const float* anchors = (const float*)d_in[4];
    float* out = (float*)d_out;

    prop_kernel<<<NCTA, 128>>>(frag, clouds, kern, W, out);
    norm_kernel<<<NBB*CON*30, 256>>>(clouds, anchors, out);
}